// round 5
// baseline (speedup 1.0000x reference)
#include <cuda_runtime.h>

// Problem constants
#define BB   8
#define CCH  64
#define HW   96
#define NL   2209    // 47*47 query/key patches
#define LPAD 2304    // padded to 18*128
#define DIM  1600    // 64*5*5 patch descriptor
#define KB   16
#define NKC  (DIM/KB)   // 100
#define NE   576     // 64*3*3 value patch dim
#define MAXFLAG 4096
#define MARGIN_TH 3e-4f
#define TIE_ZONE 8e-8   // fp64 gap below which we defer to first-occurrence rule

// Scratch (zero-initialized .bss; rows [NL, LPAD) stay zero)
__device__ float g_Qn[(size_t)BB * LPAD * DIM];
__device__ float g_Kn[(size_t)BB * LPAD * DIM];
__device__ int   g_arg[BB * NL];
__device__ int   g_nflag;
__device__ int4  g_flag[MAXFLAG];   // {b, q, best_idx, second_idx}

// ---------------------------------------------------------------------------
// Prep: unfold(5,1,2) + L2 normalize (norm accumulated in fp64).
// ---------------------------------------------------------------------------
__global__ __launch_bounds__(256) void prep_kernel(const float* __restrict__ queue,
                                                   const float* __restrict__ key) {
    int l = blockIdx.x;            // 0..2208
    int b = blockIdx.y;            // 0..7
    bool isK = (blockIdx.z != 0);
    int t = threadIdx.x;
    if (blockIdx.x == 0 && blockIdx.y == 0 && blockIdx.z == 0 && t == 0) g_nflag = 0;

    const float* src = (isK ? key : queue) + (size_t)b * CCH * HW * HW;
    float* dst = (isK ? g_Kn : g_Qn) + ((size_t)b * LPAD + l) * DIM;

    int pi = l / 47, pj = l % 47;
    int r0 = pi * 2 - 1, c0 = pj * 2 - 1;

    float vals[7];
    double ss = 0.0;
#pragma unroll
    for (int it = 0; it < 7; it++) {
        int e = t + it * 256;
        float v = 0.f;
        if (e < DIM) {
            int c = e / 25, kk = e % 25;
            int r = r0 + kk / 5, cc = c0 + kk % 5;
            if ((unsigned)r < HW && (unsigned)cc < HW)
                v = src[((size_t)c * HW + r) * HW + cc];
        }
        vals[it] = v;
        ss += (double)v * (double)v;
    }

    __shared__ double red[256];
    red[t] = ss;
    __syncthreads();
    for (int s = 128; s >= 1; s >>= 1) {
        if (t < s) red[t] += red[t + s];
        __syncthreads();
    }
    float n = (float)sqrt(red[0]);
    if (n < 1e-12f) n = 1e-12f;

#pragma unroll
    for (int it = 0; it < 7; it++) {
        int e = t + it * 256;
        if (e < DIM) dst[e] = vals[it] / n;
    }
}

// ---------------------------------------------------------------------------
// Fused correlation GEMM + column top-2 max/argmax.
// 256 threads, 128(L) x 128(Q) tile, 8x8 microtile, KB=16 double-buffered.
// ---------------------------------------------------------------------------
__global__ __launch_bounds__(256) void corr_kernel(float* __restrict__ S) {
    int b  = blockIdx.y;
    int q0 = blockIdx.x * 128;
    const float* Kb = g_Kn + (size_t)b * LPAD * DIM;
    const float* Qb = g_Qn + (size_t)b * LPAD * DIM;

    __shared__ float As[2][KB][132];   // [buf][d][l]
    __shared__ float Bs[2][KB][132];   // [buf][d][q]

    int tid = threadIdx.x;
    int tx = tid & 15, ty = tid >> 4;
    int row = tid >> 2, c4 = tid & 3;

    float best[8], second[8];
    int   bidx[8], sidx[8];
#pragma unroll
    for (int j = 0; j < 8; j++) {
        best[j] = -3.0e38f; second[j] = -3.0e38f; bidx[j] = 0; sidx[j] = 0;
    }

    for (int lt = 0; lt < 18; lt++) {
        int l0 = lt * 128;
        float acc[8][8];
#pragma unroll
        for (int i = 0; i < 8; i++)
#pragma unroll
            for (int j = 0; j < 8; j++) acc[i][j] = 0.f;

        {
            float4 a0 = *(const float4*)(Kb + (size_t)(l0 + row)      * DIM + c4 * 4);
            float4 a1 = *(const float4*)(Kb + (size_t)(l0 + row + 64) * DIM + c4 * 4);
            float4 b0 = *(const float4*)(Qb + (size_t)(q0 + row)      * DIM + c4 * 4);
            float4 b1 = *(const float4*)(Qb + (size_t)(q0 + row + 64) * DIM + c4 * 4);
            As[0][c4 * 4 + 0][row] = a0.x; As[0][c4 * 4 + 1][row] = a0.y;
            As[0][c4 * 4 + 2][row] = a0.z; As[0][c4 * 4 + 3][row] = a0.w;
            As[0][c4 * 4 + 0][row + 64] = a1.x; As[0][c4 * 4 + 1][row + 64] = a1.y;
            As[0][c4 * 4 + 2][row + 64] = a1.z; As[0][c4 * 4 + 3][row + 64] = a1.w;
            Bs[0][c4 * 4 + 0][row] = b0.x; Bs[0][c4 * 4 + 1][row] = b0.y;
            Bs[0][c4 * 4 + 2][row] = b0.z; Bs[0][c4 * 4 + 3][row] = b0.w;
            Bs[0][c4 * 4 + 0][row + 64] = b1.x; Bs[0][c4 * 4 + 1][row + 64] = b1.y;
            Bs[0][c4 * 4 + 2][row + 64] = b1.z; Bs[0][c4 * 4 + 3][row + 64] = b1.w;
        }
        __syncthreads();

        for (int kc = 0; kc < NKC; kc++) {
            int cur = kc & 1;
            float4 pa0, pa1, pb0, pb1;
            bool pf = (kc + 1 < NKC);
            if (pf) {
                int d0 = (kc + 1) * KB;
                pa0 = *(const float4*)(Kb + (size_t)(l0 + row)      * DIM + d0 + c4 * 4);
                pa1 = *(const float4*)(Kb + (size_t)(l0 + row + 64) * DIM + d0 + c4 * 4);
                pb0 = *(const float4*)(Qb + (size_t)(q0 + row)      * DIM + d0 + c4 * 4);
                pb1 = *(const float4*)(Qb + (size_t)(q0 + row + 64) * DIM + d0 + c4 * 4);
            }
#pragma unroll
            for (int d = 0; d < KB; d++) {
                float4 a0 = *(const float4*)&As[cur][d][ty * 8];
                float4 a1 = *(const float4*)&As[cur][d][ty * 8 + 4];
                float4 b0 = *(const float4*)&Bs[cur][d][tx * 8];
                float4 b1 = *(const float4*)&Bs[cur][d][tx * 8 + 4];
                float av[8] = {a0.x, a0.y, a0.z, a0.w, a1.x, a1.y, a1.z, a1.w};
                float bv[8] = {b0.x, b0.y, b0.z, b0.w, b1.x, b1.y, b1.z, b1.w};
#pragma unroll
                for (int i = 0; i < 8; i++)
#pragma unroll
                    for (int j = 0; j < 8; j++)
                        acc[i][j] = fmaf(av[i], bv[j], acc[i][j]);
            }
            if (pf) {
                int nxt = cur ^ 1;
                As[nxt][c4 * 4 + 0][row] = pa0.x; As[nxt][c4 * 4 + 1][row] = pa0.y;
                As[nxt][c4 * 4 + 2][row] = pa0.z; As[nxt][c4 * 4 + 3][row] = pa0.w;
                As[nxt][c4 * 4 + 0][row + 64] = pa1.x; As[nxt][c4 * 4 + 1][row + 64] = pa1.y;
                As[nxt][c4 * 4 + 2][row + 64] = pa1.z; As[nxt][c4 * 4 + 3][row + 64] = pa1.w;
                Bs[nxt][c4 * 4 + 0][row] = pb0.x; Bs[nxt][c4 * 4 + 1][row] = pb0.y;
                Bs[nxt][c4 * 4 + 2][row] = pb0.z; Bs[nxt][c4 * 4 + 3][row] = pb0.w;
                Bs[nxt][c4 * 4 + 0][row + 64] = pb1.x; Bs[nxt][c4 * 4 + 1][row + 64] = pb1.y;
                Bs[nxt][c4 * 4 + 2][row + 64] = pb1.z; Bs[nxt][c4 * 4 + 3][row + 64] = pb1.w;
            }
            __syncthreads();
        }

        // fold tile into running top-2 (l strictly ascending per thread)
#pragma unroll
        for (int i = 0; i < 8; i++) {
            int l = l0 + ty * 8 + i;
            if (l < NL) {
#pragma unroll
                for (int j = 0; j < 8; j++) {
                    float v = acc[i][j];
                    if (v > best[j]) {
                        second[j] = best[j]; sidx[j] = bidx[j];
                        best[j] = v; bidx[j] = l;
                    } else if (v > second[j]) {
                        second[j] = v; sidx[j] = l;
                    }
                }
            }
        }
    }

    // reduce across the 16 ty-groups (they share q columns)
    __syncthreads();
    float* sv  = &As[0][0][0];          // 2048 floats
    float* ss2 = &As[0][0][0] + 2048;   // 2048 floats (As holds 4224)
    int*   siB = (int*)&Bs[0][0][0];
    int*   siS = (int*)&Bs[0][0][0] + 2048;
#pragma unroll
    for (int j = 0; j < 8; j++) {
        int o = ty * 128 + tx * 8 + j;
        sv[o]  = best[j];   ss2[o] = second[j];
        siB[o] = bidx[j];   siS[o] = sidx[j];
    }
    __syncthreads();
    if (tid < 128) {
        float bv = sv[tid], sec = ss2[tid];
        int   bi = siB[tid], si_ = siS[tid];
#pragma unroll 1
        for (int r = 1; r < 16; r++) {
            float v  = sv[r * 128 + tid];
            float s2 = ss2[r * 128 + tid];
            int  iv  = siB[r * 128 + tid];
            int  is2 = siS[r * 128 + tid];
            if (v > bv || (v == bv && iv < bi)) {
                if (bv > s2 || (bv == s2 && bi < is2)) { sec = bv; si_ = bi; }
                else { sec = s2; si_ = is2; }
                bv = v; bi = iv;
            } else {
                if (v > sec || (v == sec && iv < si_)) { sec = v; si_ = iv; }
            }
        }
        int q = q0 + tid;
        if (q < NL) {
            S[b * NL + q]     = bv;
            g_arg[b * NL + q] = bi;
            if (bv - sec < MARGIN_TH) {
                int idx = atomicAdd(&g_nflag, 1);
                if (idx < MAXFLAG) g_flag[idx] = make_int4(b, q, bi, si_);
            }
        }
    }
}

// ---------------------------------------------------------------------------
// Refine: near-tie queries. fp64-exact comparison; if the exact gap is inside
// the reference's fp32 noise zone, defer to first-occurrence (lower index).
// ---------------------------------------------------------------------------
__global__ __launch_bounds__(32) void fix_kernel() {
    int n = g_nflag; if (n > MAXFLAG) n = MAXFLAG;
    if ((int)blockIdx.x >= n) return;
    int4 f = g_flag[blockIdx.x];
    int b = f.x, q = f.y, i1 = f.z, i2 = f.w;
    const float* K1 = g_Kn + ((size_t)b * LPAD + i1) * DIM;
    const float* K2 = g_Kn + ((size_t)b * LPAD + i2) * DIM;
    const float* Qr = g_Qn + ((size_t)b * LPAD + q) * DIM;
    int lane = threadIdx.x;
    double s1 = 0.0, s2 = 0.0;
    for (int d = lane; d < DIM; d += 32) {
        double qq = (double)Qr[d];
        s1 = fma((double)K1[d], qq, s1);
        s2 = fma((double)K2[d], qq, s2);
    }
#pragma unroll
    for (int o = 16; o; o >>= 1) {
        s1 += __shfl_down_sync(0xffffffff, s1, o);
        s2 += __shfl_down_sync(0xffffffff, s2, o);
    }
    if (lane == 0) {
        int win;
        double gap = s1 - s2;
        double ag = fabs(gap);
        if (ag < TIE_ZONE) {
            win = (i1 < i2) ? i1 : i2;        // deep tie: ref noise flips to first occurrence
        } else {
            win = (gap > 0.0) ? i1 : i2;      // exact winner
        }
        g_arg[b * NL + q] = win;
    }
}

// ---------------------------------------------------------------------------
// Gather: T[b, c*9+kh*3+kw, q] = value_padded[b, c, arg/96 + kh, arg%96 + kw]
// ---------------------------------------------------------------------------
__global__ __launch_bounds__(256) void gather_kernel(const float* __restrict__ value,
                                                     float* __restrict__ T) {
    int idx = blockIdx.x * 256 + threadIdx.x;
    const int total = BB * NE * NL;
    if (idx >= total) return;
    int q = idx % NL;
    int t = idx / NL;
    int e = t % NE;
    int b = t / NE;
    int l = g_arg[b * NL + q];
    int c = e / 9, k = e % 9;
    int kh = k / 3, kw = k % 3;
    int r  = l / 96 + kh - 1;
    int cc = l % 96 + kw - 1;
    float v = 0.f;
    if ((unsigned)r < HW && (unsigned)cc < HW)
        v = __ldg(&value[(((size_t)b * CCH + c) * HW + r) * HW + cc]);
    T[idx] = v;
}

// ---------------------------------------------------------------------------
extern "C" void kernel_launch(void* const* d_in, const int* in_sizes, int n_in,
                              void* d_out, int out_size) {
    const float* queue = (const float*)d_in[0];
    const float* key   = (const float*)d_in[1];
    const float* value = (const float*)d_in[2];
    float* out = (float*)d_out;            // layout: S (8*2209) then T (8*576*2209)

    dim3 gp(NL, BB, 2);
    prep_kernel<<<gp, 256>>>(queue, key);

    dim3 gc(18, BB);
    corr_kernel<<<gc, 256>>>(out);

    fix_kernel<<<MAXFLAG, 32>>>();

    const int total = BB * NE * NL;
    gather_kernel<<<(total + 255) / 256, 256>>>(value, out + BB * NL);
}